// round 13
// baseline (speedup 1.0000x reference)
#include <cuda_runtime.h>
#include <cuda_fp16.h>
#include <math.h>
#include <stdint.h>

#define NDIM 20000
#define DDIM 3072
#define BDIM 128
#define KB 32
#define CH1 (DDIM / KB)            /* 96 */
#define NT1 ((NDIM + 63) / 64)     /* 313 */
#define NSPLIT 6
#define SPAN2 3328                 /* splits 0-4: 52 chunks of 64; split 5: 3360 -> 53 chunks */
#define DT2 (DDIM / 64)            /* 48 */

// GEMM1 smem: per buffer 2 A-splits (128x32 fp16 = 8KB) + 2 B-splits (64x32 = 4KB)
#define SA1(s, p) ((p) * 24576 + (s) * 8192)
#define SB1(s, p) ((p) * 24576 + 16384 + (s) * 4096)
#define SM1_TOTAL (2 * 24576)
// GEMM2 smem (KB=64): per buffer E tile 128x64 (16KB) + G tile 64x64 (8KB)
#define SE2(p) ((p) * 24576)
#define SG2(p) ((p) * 24576 + 16384)
#define SM2_TOTAL (2 * 24576)

// Scratch (allocation-free rule: __device__ globals)
__device__ float g_s[BDIM * NDIM];               // logits
__device__ float g_rowsum[BDIM];
__device__ __half g_eh[BDIM * NDIM];             // e = exp(s - m) in fp16
__device__ float g_part[NSPLIT * BDIM * DDIM];

// Swizzled byte offset inside a [rows x 32k] fp16 tile (row stride 64B).
__device__ __forceinline__ int toff(int row, int k)
{
    return row * 64 + ((((k >> 3) & 3) ^ ((row >> 1) & 3)) << 4) + ((k * 2) & 15);
}
// Swizzled byte offset inside a [rows x 64k] fp16 tile (row stride 128B).
__device__ __forceinline__ int toff64(int row, int k)
{
    return row * 128 + ((((k >> 3) & 7) ^ (row & 7)) << 4) + ((k * 2) & 15);
}

__device__ __forceinline__ uint32_t pk2h(float a, float b)
{
    __half2 t = __floats2half2_rn(a, b);
    return *reinterpret_cast<uint32_t*>(&t);
}
__device__ __forceinline__ void split2h_u4(const float v[8], uint4& uh, uint4& ul)
{
    float h[8], l[8];
#pragma unroll
    for (int i = 0; i < 8; i++) {
        h[i] = __half2float(__float2half_rn(v[i]));
        l[i] = v[i] - h[i];
    }
    uh = make_uint4(pk2h(h[0], h[1]), pk2h(h[2], h[3]), pk2h(h[4], h[5]), pk2h(h[6], h[7]));
    ul = make_uint4(pk2h(l[0], l[1]), pk2h(l[2], l[3]), pk2h(l[4], l[5]), pk2h(l[6], l[7]));
}
__device__ __forceinline__ void mma_f32acc(float c[4], const uint32_t a[4], const uint32_t b[2])
{
    asm volatile(
        "mma.sync.aligned.m16n8k16.row.col.f32.f16.f16.f32 "
        "{%0,%1,%2,%3}, {%4,%5,%6,%7}, {%8,%9}, {%0,%1,%2,%3};"
        : "+f"(c[0]), "+f"(c[1]), "+f"(c[2]), "+f"(c[3])
        : "r"(a[0]), "r"(a[1]), "r"(a[2]), "r"(a[3]), "r"(b[0]), "r"(b[1]));
}
__device__ __forceinline__ void mma_f16acc(uint32_t c[2], const uint32_t a[4], const uint32_t b[2])
{
    asm volatile(
        "mma.sync.aligned.m16n8k16.row.col.f16.f16.f16.f16 "
        "{%0,%1}, {%2,%3,%4,%5}, {%6,%7}, {%0,%1};"
        : "+r"(c[0]), "+r"(c[1])
        : "r"(a[0]), "r"(a[1]), "r"(a[2]), "r"(a[3]), "r"(b[0]), "r"(b[1]));
}
__device__ __forceinline__ float lo2f(uint32_t u) { return __low2float(*reinterpret_cast<__half2*>(&u)); }
__device__ __forceinline__ float hi2f(uint32_t u) { return __high2float(*reinterpret_cast<__half2*>(&u)); }

// ---- GEMM1 fragment helpers (KB=32 tiles, toff) ----
#define LOAD_AFRAGS(SRC)                                                       \
    do {                                                                       \
        _Pragma("unroll")                                                      \
        for (int mt = 0; mt < 2; mt++)                                         \
            _Pragma("unroll")                                                  \
            for (int ks = 0; ks < 2; ks++) {                                   \
                const int row = wm + mt * 16 + (lane >> 2);                    \
                const int kq = ks * 16 + (lane & 3) * 2;                       \
                af[mt][ks][0] = *(const uint32_t*)((SRC) + toff(row, kq));     \
                af[mt][ks][1] = *(const uint32_t*)((SRC) + toff(row + 8, kq)); \
                af[mt][ks][2] = *(const uint32_t*)((SRC) + toff(row, kq + 8)); \
                af[mt][ks][3] = *(const uint32_t*)((SRC) + toff(row + 8, kq + 8)); \
            }                                                                  \
    } while (0)

#define MMA_PASS_F32(BSRC)                                                     \
    do {                                                                       \
        _Pragma("unroll")                                                      \
        for (int ks = 0; ks < 2; ks++)                                         \
            _Pragma("unroll")                                                  \
            for (int nt = 0; nt < 4; nt++) {                                   \
                const int col = wn + nt * 8 + (lane >> 2);                     \
                const int kq = ks * 16 + (lane & 3) * 2;                       \
                uint32_t bf[2];                                                \
                bf[0] = *(const uint32_t*)((BSRC) + toff(col, kq));            \
                bf[1] = *(const uint32_t*)((BSRC) + toff(col, kq + 8));        \
                _Pragma("unroll")                                              \
                for (int mt = 0; mt < 2; mt++) mma_f32acc(acc[mt][nt], af[mt][ks], bf); \
            }                                                                  \
    } while (0)

#define MMA_PASS_F16(BSRC)                                                     \
    do {                                                                       \
        _Pragma("unroll")                                                      \
        for (int ks = 0; ks < 2; ks++)                                         \
            _Pragma("unroll")                                                  \
            for (int nt = 0; nt < 4; nt++) {                                   \
                const int col = wn + nt * 8 + (lane >> 2);                     \
                const int kq = ks * 16 + (lane & 3) * 2;                       \
                uint32_t bf[2];                                                \
                bf[0] = *(const uint32_t*)((BSRC) + toff(col, kq));            \
                bf[1] = *(const uint32_t*)((BSRC) + toff(col, kq + 8));        \
                _Pragma("unroll")                                              \
                for (int mt = 0; mt < 2; mt++) mma_f16acc(ach[mt][nt], af[mt][ks], bf); \
            }                                                                  \
    } while (0)

// ---------------------------------------------------------------------------
// GEMM1: s[b,n] = alpha[b]*(x_b.gt_n) - beta[b]*||gt_n||^2
// CTA tile 128b x 64n, KB=32, double-buffered.
// 3 passes: hh (f32 acc) + hl, lh (f16 acc) — required (alpha amplification).
// ---------------------------------------------------------------------------
__global__ __launch_bounds__(256, 2) void gemm1_kernel(const float* __restrict__ x,
                                                       const float* __restrict__ t,
                                                       const float* __restrict__ gt)
{
    extern __shared__ char sm[];
    __shared__ float alpha_s[128], beta_s[128], g2s[64];

    const int tid = threadIdx.x, lane = tid & 31, warp = tid >> 5;
    const int wm = (warp & 3) * 32, wn = (warp >> 2) * 32;
    const int nblk = blockIdx.x * 64;

    if (tid < 128) {
        const float tt = t[tid] * (1.0f / 999.0f);
        const float sg = 1.0f - tt;
        const float inv = 1.0f / (sg * sg);
        alpha_s[tid] = tt * inv;
        beta_s[tid] = 0.5f * tt * tt * inv;
    }

    const int ar = tid >> 1, akh = (tid & 1) * 16;
    const int br = tid >> 2, bk8 = (tid & 3) * 8;
    const int gn = nblk + br;
    const bool gvalid = (gn < NDIM);
    const float* xp = x + (size_t)ar * DDIM + akh;
    const float* gp = gt + (size_t)gn * DDIM + bk8;

    float acc[2][4][4];
    uint32_t ach[2][4][2];
#pragma unroll
    for (int a = 0; a < 2; a++)
#pragma unroll
        for (int b = 0; b < 4; b++) {
#pragma unroll
            for (int e = 0; e < 4; e++) acc[a][b][e] = 0.0f;
            ach[a][b][0] = 0u; ach[a][b][1] = 0u;
        }
    float g2a = 0.0f;
    float xv[16], gv[8];

#define LOAD_G1(kc)                                                        \
    do {                                                                   \
        float4 _a0 = *(const float4*)(xp + (kc));                          \
        float4 _a1 = *(const float4*)(xp + (kc) + 4);                      \
        float4 _a2 = *(const float4*)(xp + (kc) + 8);                      \
        float4 _a3 = *(const float4*)(xp + (kc) + 12);                     \
        xv[0]=_a0.x; xv[1]=_a0.y; xv[2]=_a0.z; xv[3]=_a0.w;                \
        xv[4]=_a1.x; xv[5]=_a1.y; xv[6]=_a1.z; xv[7]=_a1.w;                \
        xv[8]=_a2.x; xv[9]=_a2.y; xv[10]=_a2.z; xv[11]=_a2.w;              \
        xv[12]=_a3.x; xv[13]=_a3.y; xv[14]=_a3.z; xv[15]=_a3.w;            \
        if (gvalid) {                                                      \
            float4 _b0 = *(const float4*)(gp + (kc));                      \
            float4 _b1 = *(const float4*)(gp + (kc) + 4);                  \
            gv[0]=_b0.x; gv[1]=_b0.y; gv[2]=_b0.z; gv[3]=_b0.w;            \
            gv[4]=_b1.x; gv[5]=_b1.y; gv[6]=_b1.z; gv[7]=_b1.w;            \
        } else {                                                           \
            _Pragma("unroll") for (int _i = 0; _i < 8; _i++) gv[_i] = 0.0f;\
        }                                                                  \
    } while (0)

#define STORE_G1(pb)                                                       \
    do {                                                                   \
        _Pragma("unroll")                                                  \
        for (int _g = 0; _g < 2; _g++) {                                   \
            uint4 _uh, _ul;                                                \
            split2h_u4(xv + _g * 8, _uh, _ul);                             \
            const int _o = toff(ar, akh + _g * 8);                         \
            *(uint4*)(sm + SA1(0, pb) + _o) = _uh;                         \
            *(uint4*)(sm + SA1(1, pb) + _o) = _ul;                         \
        }                                                                  \
        {                                                                  \
            uint4 _uh, _ul;                                                \
            split2h_u4(gv, _uh, _ul);                                      \
            _Pragma("unroll") for (int _i = 0; _i < 8; _i++) g2a += gv[_i] * gv[_i]; \
            const int _o = toff(br, bk8);                                  \
            *(uint4*)(sm + SB1(0, pb) + _o) = _uh;                         \
            *(uint4*)(sm + SB1(1, pb) + _o) = _ul;                         \
        }                                                                  \
    } while (0)

    LOAD_G1(0);
    STORE_G1(0);
    __syncthreads();

    for (int c = 0; c < CH1; c++) {
        const int p = c & 1;
        const bool more = (c + 1 < CH1);
        if (more) LOAD_G1((c + 1) * KB);

        {
            uint32_t af[2][2][4];
            LOAD_AFRAGS(sm + SA1(0, p));          // xh
            MMA_PASS_F32(sm + SB1(0, p));          // xh*gh
            MMA_PASS_F16(sm + SB1(1, p));          // xh*gl
            LOAD_AFRAGS(sm + SA1(1, p));          // xl
            MMA_PASS_F16(sm + SB1(0, p));          // xl*gh
        }

        if (more) STORE_G1(p ^ 1);
        __syncthreads();
    }

    g2a += __shfl_xor_sync(0xffffffffu, g2a, 1);
    g2a += __shfl_xor_sync(0xffffffffu, g2a, 2);
    if ((tid & 3) == 0) g2s[br] = g2a;
    __syncthreads();

#pragma unroll
    for (int mt = 0; mt < 2; mt++) {
#pragma unroll
        for (int nt = 0; nt < 4; nt++) {
            const int lc = wn + nt * 8 + (lane & 3) * 2;
            const int n = nblk + lc;
            if (n >= NDIM) continue;
            const int row0 = wm + mt * 16 + (lane >> 2);
            const float a0 = alpha_s[row0], b0 = beta_s[row0];
            const float a1 = alpha_s[row0 + 8], b1 = beta_s[row0 + 8];
            const float q0 = g2s[lc], q1 = g2s[lc + 1];
            const float v00 = acc[mt][nt][0] + lo2f(ach[mt][nt][0]);
            const float v01 = acc[mt][nt][1] + hi2f(ach[mt][nt][0]);
            const float v10 = acc[mt][nt][2] + lo2f(ach[mt][nt][1]);
            const float v11 = acc[mt][nt][3] + hi2f(ach[mt][nt][1]);
            *(float2*)&g_s[(size_t)row0 * NDIM + n] = make_float2(a0 * v00 - b0 * q0, a0 * v01 - b0 * q1);
            *(float2*)&g_s[(size_t)(row0 + 8) * NDIM + n] = make_float2(a1 * v10 - b1 * q0, a1 * v11 - b1 * q1);
        }
    }
#undef LOAD_G1
#undef STORE_G1
}

// ---------------------------------------------------------------------------
// Softmax stats: rowmax; unnormalized e = exp(s-m) -> fp16; rowsum.
// ---------------------------------------------------------------------------
__global__ __launch_bounds__(256) void softmax_stats_kernel()
{
    const int b = blockIdx.x;
    const int tid = threadIdx.x;
    const float* row = g_s + (size_t)b * NDIM;
    __shared__ float red[256];

    float m = -INFINITY;
    for (int i = tid; i < NDIM; i += 256) m = fmaxf(m, row[i]);
    red[tid] = m;
    __syncthreads();
    for (int s = 128; s > 0; s >>= 1) {
        if (tid < s) red[tid] = fmaxf(red[tid], red[tid + s]);
        __syncthreads();
    }
    m = red[0];
    __syncthreads();

    float sum = 0.0f;
    for (int i = tid; i < NDIM; i += 256) {
        const float e = __expf(row[i] - m);
        sum += e;
        g_eh[(size_t)b * NDIM + i] = __float2half_rn(e);
    }
    red[tid] = sum;
    __syncthreads();
    for (int s = 128; s > 0; s >>= 1) {
        if (tid < s) red[tid] += red[tid + s];
        __syncthreads();
    }
    if (tid == 0) g_rowsum[b] = red[0];
}

// ---------------------------------------------------------------------------
// GEMM2: partial[b,d] = sum_n e[b,n]*gt[n,d].  CTA tile 128b x 64d, KB=64 (n).
// Single pass eh*gh (f32 acc). 128B-row swizzle (toff64).
// ---------------------------------------------------------------------------
__global__ __launch_bounds__(256, 2) void gemm2_kernel(const float* __restrict__ gt)
{
    extern __shared__ char sm[];
    const int tid = threadIdx.x, lane = tid & 31, warp = tid >> 5;
    const int wm = (warp & 3) * 32, wn = (warp >> 2) * 32;
    const int dblk = blockIdx.x * 64;
    const int nbase = blockIdx.y * SPAN2;
    const int ch = (blockIdx.y == NSPLIT - 1) ? 53 : 52;   /* last split spans 3360 */

    // producer roles
    const int er = tid >> 1, ekh = (tid & 1) * 32;          // E: row er, 32 n's
    const int gn2 = (tid & 31) * 2, gdg = (tid >> 5) * 8;   // G: 2 n-rows x 8 d

    float acc[2][4][4];
#pragma unroll
    for (int a = 0; a < 2; a++)
#pragma unroll
        for (int b = 0; b < 4; b++)
#pragma unroll
            for (int e = 0; e < 4; e++) acc[a][b][e] = 0.0f;

    uint4 ev[4];
    float gva[8], gvb[8];

#define LOAD_G2(n0)                                                        \
    do {                                                                   \
        const size_t _eo = (size_t)er * NDIM + (n0) + ekh;                 \
        _Pragma("unroll")                                                  \
        for (int _j = 0; _j < 4; _j++)                                     \
            ev[_j] = ((n0) + ekh + _j * 8 < NDIM) ? *(const uint4*)&g_eh[_eo + _j * 8] \
                                                  : make_uint4(0, 0, 0, 0);\
        if ((n0) + gn2 < NDIM) {                                           \
            const float* _ga = gt + (size_t)((n0) + gn2) * DDIM + dblk + gdg;       \
            const float* _gb = gt + (size_t)((n0) + gn2 + 1) * DDIM + dblk + gdg;   \
            float4 _f = *(const float4*)(_ga);                             \
            gva[0]=_f.x; gva[1]=_f.y; gva[2]=_f.z; gva[3]=_f.w;            \
            _f = *(const float4*)(_ga + 4);                                \
            gva[4]=_f.x; gva[5]=_f.y; gva[6]=_f.z; gva[7]=_f.w;            \
            _f = *(const float4*)(_gb);                                    \
            gvb[0]=_f.x; gvb[1]=_f.y; gvb[2]=_f.z; gvb[3]=_f.w;            \
            _f = *(const float4*)(_gb + 4);                                \
            gvb[4]=_f.x; gvb[5]=_f.y; gvb[6]=_f.z; gvb[7]=_f.w;            \
        } else {                                                           \
            _Pragma("unroll")                                              \
            for (int _i = 0; _i < 8; _i++) { gva[_i] = 0.0f; gvb[_i] = 0.0f; } \
        }                                                                  \
    } while (0)

#define STORE_G2(pb)                                                       \
    do {                                                                   \
        _Pragma("unroll")                                                  \
        for (int _j = 0; _j < 4; _j++)                                     \
            *(uint4*)(sm + SE2(pb) + toff64(er, ekh + _j * 8)) = ev[_j];   \
        _Pragma("unroll")                                                  \
        for (int _j = 0; _j < 8; _j++) {                                   \
            const int _o = toff64(gdg + _j, gn2);                          \
            *(uint32_t*)(sm + SG2(pb) + _o) = pk2h(gva[_j], gvb[_j]);      \
        }                                                                  \
    } while (0)

    LOAD_G2(nbase);
    STORE_G2(0);
    __syncthreads();

    for (int c = 0; c < ch; c++) {
        const int p = c & 1;
        const bool more = (c + 1 < ch);
        if (more) LOAD_G2(nbase + (c + 1) * 64);

        // MMA: 4 k-sections of 16, single pass eh*gh
        {
            const char* A = sm + SE2(p);
            const char* B = sm + SG2(p);
#pragma unroll
            for (int ks = 0; ks < 4; ks++) {
                uint32_t af[2][4];
#pragma unroll
                for (int mt = 0; mt < 2; mt++) {
                    const int row = wm + mt * 16 + (lane >> 2);
                    const int kq = ks * 16 + (lane & 3) * 2;
                    af[mt][0] = *(const uint32_t*)(A + toff64(row, kq));
                    af[mt][1] = *(const uint32_t*)(A + toff64(row + 8, kq));
                    af[mt][2] = *(const uint32_t*)(A + toff64(row, kq + 8));
                    af[mt][3] = *(const uint32_t*)(A + toff64(row + 8, kq + 8));
                }
#pragma unroll
                for (int nt = 0; nt < 4; nt++) {
                    const int col = wn + nt * 8 + (lane >> 2);
                    const int kq = ks * 16 + (lane & 3) * 2;
                    uint32_t bf[2];
                    bf[0] = *(const uint32_t*)(B + toff64(col, kq));
                    bf[1] = *(const uint32_t*)(B + toff64(col, kq + 8));
#pragma unroll
                    for (int mt = 0; mt < 2; mt++) mma_f32acc(acc[mt][nt], af[mt], bf);
                }
            }
        }

        if (more) STORE_G2(p ^ 1);
        __syncthreads();
    }

    float* outp = g_part + (size_t)blockIdx.y * BDIM * DDIM;
#pragma unroll
    for (int mt = 0; mt < 2; mt++)
#pragma unroll
        for (int nt = 0; nt < 4; nt++) {
            const int row0 = wm + mt * 16 + (lane >> 2);
            const int col = dblk + wn + nt * 8 + (lane & 3) * 2;
            *(float2*)&outp[(size_t)row0 * DDIM + col] = make_float2(acc[mt][nt][0], acc[mt][nt][1]);
            *(float2*)&outp[(size_t)(row0 + 8) * DDIM + col] = make_float2(acc[mt][nt][2], acc[mt][nt][3]);
        }
#undef LOAD_G2
#undef STORE_G2
}

// ---------------------------------------------------------------------------
// Epilogue: out = (sum_splits partial / rowsum - x) / sig
// ---------------------------------------------------------------------------
__global__ __launch_bounds__(256) void epilogue_kernel(const float* __restrict__ x,
                                                       const float* __restrict__ t,
                                                       float* __restrict__ out)
{
    const int idx = blockIdx.x * 256 + threadIdx.x;
    if (idx >= BDIM * DDIM) return;
    const int b = idx / DDIM;
    float a = 0.0f;
#pragma unroll
    for (int s = 0; s < NSPLIT; s++) a += g_part[(size_t)s * BDIM * DDIM + idx];
    const float tt = t[b] * (1.0f / 999.0f);
    const float sg = 1.0f - tt;
    out[idx] = (a / g_rowsum[b] - x[idx]) / sg;
}

extern "C" void kernel_launch(void* const* d_in, const int* in_sizes, int n_in,
                              void* d_out, int out_size)
{
    const float* xt = (const float*)d_in[0];
    const float* t  = (const float*)d_in[1];
    const float* gt = (const float*)d_in[2];
    float* out = (float*)d_out;

    static int attr_done = 0;
    if (!attr_done) {
        cudaFuncSetAttribute(gemm1_kernel, cudaFuncAttributeMaxDynamicSharedMemorySize, SM1_TOTAL);
        cudaFuncSetAttribute(gemm2_kernel, cudaFuncAttributeMaxDynamicSharedMemorySize, SM2_TOTAL);
        attr_done = 1;
    }

    gemm1_kernel<<<NT1, 256, SM1_TOTAL>>>(xt, t, gt);
    softmax_stats_kernel<<<BDIM, 256>>>();
    dim3 g2(DT2, NSPLIT);
    gemm2_kernel<<<g2, 256, SM2_TOTAL>>>(gt);
    epilogue_kernel<<<(BDIM * DDIM + 255) / 256, 256>>>(xt, t, out);
}